// round 3
// baseline (speedup 1.0000x reference)
#include <cuda_runtime.h>
#include <cuda_bf16.h>
#include <stdint.h>

#define NB 96
#define NQ 96
#define NV 197
#define NT 77
#define ND 768
#define NE 512
#define RV (NB*NV)
#define RT (NQ*NT)

// scratch (static device globals — no allocation allowed)
__device__ float g_Pv[RV*NE];
__device__ float g_Pt[RT*NE];
__device__ __nv_bfloat16 g_vtok[RV*NE];
__device__ __nv_bfloat16 g_ttok[RT*NE];

__device__ __forceinline__ uint32_t smem_u32(const void* p){
    return (uint32_t)__cvta_generic_to_shared(p);
}
__device__ __forceinline__ void cp16(uint32_t dst, const void* src, int sz){
    asm volatile("cp.async.cg.shared.global [%0], [%1], 16, %2;\n"
                 :: "r"(dst), "l"(src), "r"(sz));
}
__device__ __forceinline__ void cp_commit(){ asm volatile("cp.async.commit_group;\n"); }
template<int N> __device__ __forceinline__ void cp_wait(){
    asm volatile("cp.async.wait_group %0;\n" :: "n"(N));
}
__device__ __forceinline__ uint32_t f2tf(float f){
    uint32_t u; asm("cvt.rna.tf32.f32 %0, %1;\n" : "=r"(u) : "f"(f)); return u;
}
__device__ __forceinline__ void mma_bf16(float c[4], const uint32_t a[4], const uint32_t b[2]){
    asm volatile(
      "mma.sync.aligned.m16n8k16.row.col.f32.bf16.bf16.f32 "
      "{%0,%1,%2,%3},{%4,%5,%6,%7},{%8,%9},{%0,%1,%2,%3};\n"
      : "+f"(c[0]),"+f"(c[1]),"+f"(c[2]),"+f"(c[3])
      : "r"(a[0]),"r"(a[1]),"r"(a[2]),"r"(a[3]),"r"(b[0]),"r"(b[1]));
}
__device__ __forceinline__ void mma_tf32(float c[4], const uint32_t a[4], const uint32_t b[2]){
    asm volatile(
      "mma.sync.aligned.m16n8k8.row.col.f32.tf32.tf32.f32 "
      "{%0,%1,%2,%3},{%4,%5,%6,%7},{%8,%9},{%0,%1,%2,%3};\n"
      : "+f"(c[0]),"+f"(c[1]),"+f"(c[2]),"+f"(c[3])
      : "r"(a[0]),"r"(a[1]),"r"(a[2]),"r"(a[3]),"r"(b[0]),"r"(b[1]));
}

// ---------------------------------------------------------------------------
// K1: cls projections (pure FP32, accuracy-critical outputs)
// grid (6, 8, 2): 16x64 tiles over [96, 512]; z = visual/textual.
// ---------------------------------------------------------------------------
__global__ __launch_bounds__(256) void cls_gemm(
    const float* __restrict__ Xv, const float* __restrict__ Xt,
    const float* __restrict__ Wv, const float* __restrict__ bv,
    const float* __restrict__ Wt, const float* __restrict__ bt,
    float* __restrict__ out)
{
    __shared__ float Xs[16][64];
    __shared__ float Ws[64][65];
    const int which = blockIdx.z;
    const float* X    = which ? Xt : Xv;
    const float* W    = which ? Wt : Wv;
    const float* bias = which ? bt : bv;
    const int m0 = blockIdx.x * 16;
    const int n0 = blockIdx.y * 64;
    const int tid = threadIdx.x;
    float acc[4] = {0.f,0.f,0.f,0.f};
    const int jj = tid & 63;
    const int r4 = (tid >> 6) * 4;

    for (int k0 = 0; k0 < ND; k0 += 64){
        {
            int r = tid >> 4, kv = tid & 15;
            float4 x4 = *(const float4*)(X + (size_t)(m0 + r)*ND + k0 + kv*4);
            Xs[r][kv*4+0]=x4.x; Xs[r][kv*4+1]=x4.y; Xs[r][kv*4+2]=x4.z; Xs[r][kv*4+3]=x4.w;
        }
        #pragma unroll
        for (int i = 0; i < 4; i++){
            int seg = tid + 256*i; int r = seg >> 4, kv = seg & 15;
            float4 w4 = *(const float4*)(W + (size_t)(n0 + r)*ND + k0 + kv*4);
            Ws[r][kv*4+0]=w4.x; Ws[r][kv*4+1]=w4.y; Ws[r][kv*4+2]=w4.z; Ws[r][kv*4+3]=w4.w;
        }
        __syncthreads();
        #pragma unroll
        for (int k = 0; k < 64; k++){
            float w = Ws[jj][k];
            acc[0] += Xs[r4+0][k]*w;
            acc[1] += Xs[r4+1][k]*w;
            acc[2] += Xs[r4+2][k]*w;
            acc[3] += Xs[r4+3][k]*w;
        }
        __syncthreads();
    }
    float bb = bias[n0 + jj];
    float* o = out + (size_t)which*(NB*NE);
    #pragma unroll
    for (int i = 0; i < 4; i++)
        o[(size_t)(m0 + r4 + i)*NE + n0 + jj] = acc[i] + bb;
}

// ---------------------------------------------------------------------------
// K2: token projection GEMM (TF32 mma.sync m16n8k8), 128x128 tile, KC=16,
// double-buffered cp.async. Writes unnormalized fp32 to g_Pv / g_Pt.
// ---------------------------------------------------------------------------
__global__ __launch_bounds__(256,2) void tok_gemm(
    const float* __restrict__ X, const float* __restrict__ W,
    const float* __restrict__ bias, int R, int which)
{
    __shared__ float As[2][128][20];
    __shared__ float Bs[2][128][20];
    float* P = which ? g_Pt : g_Pv;
    const int m0 = blockIdx.x*128, n0 = blockIdx.y*128;
    const int tid = threadIdx.x, lane = tid & 31, warp = tid >> 5;
    const int wm = warp & 1, wn = warp >> 1;   // 2 x 4 warp grid
    float acc[4][4][4] = {};
    const uint32_t aB = smem_u32(&As[0][0][0]);
    const uint32_t bB = smem_u32(&Bs[0][0][0]);

    auto loadP = [&](int buf, int kc){
        const int k0 = kc*16;
        #pragma unroll
        for (int i = 0; i < 2; i++){
            int seg = tid + 256*i; int r = seg >> 2, kv = seg & 3;
            uint32_t dst = aB + (uint32_t)(buf*128*20 + r*20 + kv*4)*4;
            int gr = m0 + r;
            const float* src = X + (size_t)(gr < R ? gr : 0)*ND + k0 + kv*4;
            cp16(dst, src, gr < R ? 16 : 0);
        }
        #pragma unroll
        for (int i = 0; i < 2; i++){
            int seg = tid + 256*i; int r = seg >> 2, kv = seg & 3;
            uint32_t dst = bB + (uint32_t)(buf*128*20 + r*20 + kv*4)*4;
            const float* src = W + (size_t)(n0 + r)*ND + k0 + kv*4;
            cp16(dst, src, 16);
        }
    };

    loadP(0, 0); cp_commit();
    for (int kc = 0; kc < 48; kc++){
        if (kc < 47){ loadP((kc+1)&1, kc+1); cp_commit(); cp_wait<1>(); }
        else        { cp_wait<0>(); }
        __syncthreads();
        const int buf = kc & 1;
        #pragma unroll
        for (int ks = 0; ks < 2; ks++){
            const int kk = ks*8 + (lane & 3);
            uint32_t a[4][4], bfr[4][2];
            #pragma unroll
            for (int mt = 0; mt < 4; mt++){
                int r = wm*64 + mt*16 + (lane >> 2);
                a[mt][0] = f2tf(As[buf][r  ][kk  ]);
                a[mt][1] = f2tf(As[buf][r+8][kk  ]);
                a[mt][2] = f2tf(As[buf][r  ][kk+4]);
                a[mt][3] = f2tf(As[buf][r+8][kk+4]);
            }
            #pragma unroll
            for (int nt = 0; nt < 4; nt++){
                int n = wn*32 + nt*8 + (lane >> 2);
                bfr[nt][0] = f2tf(Bs[buf][n][kk  ]);
                bfr[nt][1] = f2tf(Bs[buf][n][kk+4]);
            }
            #pragma unroll
            for (int mt = 0; mt < 4; mt++)
                #pragma unroll
                for (int nt = 0; nt < 4; nt++)
                    mma_tf32(acc[mt][nt], a[mt], bfr[nt]);
        }
        __syncthreads();
    }
    #pragma unroll
    for (int mt = 0; mt < 4; mt++){
        #pragma unroll
        for (int nt = 0; nt < 4; nt++){
            int r = m0 + wm*64 + mt*16 + (lane >> 2);
            int c = n0 + wn*32 + nt*8 + (lane & 3)*2;
            float b0 = bias[c], b1 = bias[c+1];
            if (r < R){
                P[(size_t)r*NE + c  ] = acc[mt][nt][0] + b0;
                P[(size_t)r*NE + c+1] = acc[mt][nt][1] + b1;
            }
            if (r + 8 < R){
                P[(size_t)(r+8)*NE + c  ] = acc[mt][nt][2] + b0;
                P[(size_t)(r+8)*NE + c+1] = acc[mt][nt][3] + b1;
            }
        }
    }
}

// ---------------------------------------------------------------------------
// K3: l2-normalize rows of P -> bf16 tokens. One warp per 512-float row.
// ---------------------------------------------------------------------------
__global__ __launch_bounds__(256) void norm_kernel(int R, int which)
{
    const float* P = which ? g_Pt : g_Pv;
    __nv_bfloat16* O = which ? g_ttok : g_vtok;
    const int row  = blockIdx.x*8 + (threadIdx.x >> 5);
    const int lane = threadIdx.x & 31;
    if (row >= R) return;
    const float4* p = (const float4*)(P + (size_t)row*NE);
    float4 v[4]; float ss = 0.f;
    #pragma unroll
    for (int i = 0; i < 4; i++){
        v[i] = p[lane + 32*i];
        ss += v[i].x*v[i].x + v[i].y*v[i].y + v[i].z*v[i].z + v[i].w*v[i].w;
    }
    #pragma unroll
    for (int o = 16; o > 0; o >>= 1) ss += __shfl_xor_sync(0xffffffffu, ss, o);
    const float s = 1.f / fmaxf(sqrtf(ss), 1e-12f);
    uint2* ob = (uint2*)(O + (size_t)row*NE);
    #pragma unroll
    for (int i = 0; i < 4; i++){
        __nv_bfloat162 lo = __floats2bfloat162_rn(v[i].x*s, v[i].y*s);
        __nv_bfloat162 hi = __floats2bfloat162_rn(v[i].z*s, v[i].w*s);
        uint2 u; u.x = *(uint32_t*)&lo; u.y = *(uint32_t*)&hi;
        ob[lane + 32*i] = u;
    }
}

// ---------------------------------------------------------------------------
// K4: fused fine-grained similarity + masked reductions. One CTA per (q, b).
// C[256pad, 80pad] = v_tok[b] @ t_tok[q]^T via bf16 m16n8k16, K=512 in
// 8 chunks of 64, double-buffered cp.async. Epilogue: spill C to smem,
// masked col-max -> t2v, masked row-max (0-clamped when len<T) -> v2t.
// ---------------------------------------------------------------------------
#define FG_SMEM 96768

__global__ __launch_bounds__(256) void fg_kernel(
    const int* __restrict__ text_length, float* __restrict__ out)
{
    extern __shared__ char smem[];
    __nv_bfloat16* As = (__nv_bfloat16*)smem;                  // [2][256][72]
    __nv_bfloat16* Bs = (__nv_bfloat16*)(smem + 2*256*72*2);   // [2][80][72]
    const int q = blockIdx.x, b = blockIdx.y;
    const int tid = threadIdx.x, lane = tid & 31, warp = tid >> 5;
    const int wm = warp >> 1, wn = warp & 1;   // 4 x 2 warps: 64 rows x 40 cols each
    const __nv_bfloat16* Ag = g_vtok + (size_t)b*NV*NE;
    const __nv_bfloat16* Bg = g_ttok + (size_t)q*NT*NE;
    float acc[4][5][4] = {};
    const uint32_t aB = smem_u32(As), bB = smem_u32(Bs);

    auto loadc = [&](int buf, int kc){
        const int k0 = kc*64;
        #pragma unroll
        for (int i = 0; i < 8; i++){           // A: 256 rows x 4x16B
            int seg = tid + 256*i; int r = seg >> 3, kv = seg & 7;
            uint32_t dst = aB + (uint32_t)(buf*256*72 + r*72 + kv*8)*2;
            const __nv_bfloat16* src = Ag + (size_t)(r < NV ? r : 0)*NE + k0 + kv*8;
            cp16(dst, src, r < NV ? 16 : 0);
        }
        #pragma unroll
        for (int i = 0; i < 3; i++){           // B: 80 rows
            int seg = tid + 256*i;
            if (seg < 640){
                int r = seg >> 3, kv = seg & 7;
                uint32_t dst = bB + (uint32_t)(buf*80*72 + r*72 + kv*8)*2;
                const __nv_bfloat16* src = Bg + (size_t)(r < NT ? r : 0)*NE + k0 + kv*8;
                cp16(dst, src, r < NT ? 16 : 0);
            }
        }
    };

    loadc(0, 0); cp_commit();
    for (int kc = 0; kc < 8; kc++){
        if (kc < 7){ loadc((kc+1)&1, kc+1); cp_commit(); cp_wait<1>(); }
        else       { cp_wait<0>(); }
        __syncthreads();
        const __nv_bfloat16* Ab = As + (size_t)(kc&1)*256*72;
        const __nv_bfloat16* Bb = Bs + (size_t)(kc&1)*80*72;
        #pragma unroll
        for (int ks = 0; ks < 4; ks++){
            const int kb = ks*16 + 2*(lane & 3);
            uint32_t a[4][4], bfr[5][2];
            #pragma unroll
            for (int mt = 0; mt < 4; mt++){
                int r = wm*64 + mt*16 + (lane >> 2);
                a[mt][0] = *(const uint32_t*)&Ab[(size_t)r    *72 + kb    ];
                a[mt][1] = *(const uint32_t*)&Ab[(size_t)(r+8)*72 + kb    ];
                a[mt][2] = *(const uint32_t*)&Ab[(size_t)r    *72 + kb + 8];
                a[mt][3] = *(const uint32_t*)&Ab[(size_t)(r+8)*72 + kb + 8];
            }
            #pragma unroll
            for (int nt = 0; nt < 5; nt++){
                int n = wn*40 + nt*8 + (lane >> 2);
                bfr[nt][0] = *(const uint32_t*)&Bb[(size_t)n*72 + kb    ];
                bfr[nt][1] = *(const uint32_t*)&Bb[(size_t)n*72 + kb + 8];
            }
            #pragma unroll
            for (int mt = 0; mt < 4; mt++)
                #pragma unroll
                for (int nt = 0; nt < 5; nt++)
                    mma_bf16(acc[mt][nt], a[mt], bfr[nt]);
        }
        __syncthreads();
    }

    // ---- epilogue: spill C, masked reductions ----
    float* C = (float*)smem;              // [256][84]
    const int CS = 84;
    float* pm  = C + 256*84;              // [3][80] col-max partials
    float* cm  = pm + 240;                // [80]
    float* red = cm + 80;                 // [8]
    #pragma unroll
    for (int mt = 0; mt < 4; mt++){
        #pragma unroll
        for (int nt = 0; nt < 5; nt++){
            int r = wm*64 + mt*16 + (lane >> 2);
            int c = wn*40 + nt*8 + (lane & 3)*2;
            C[(size_t)r    *CS + c  ] = acc[mt][nt][0];
            C[(size_t)r    *CS + c+1] = acc[mt][nt][1];
            C[(size_t)(r+8)*CS + c  ] = acc[mt][nt][2];
            C[(size_t)(r+8)*CS + c+1] = acc[mt][nt][3];
        }
    }
    __syncthreads();

    const int len = text_length[q];

    // partial column max over v (3 slices x 80 cols)
    if (tid < 240){
        int t = tid % 80, slice = tid / 80;
        int v0 = slice*66, v1 = min(v0 + 66, NV);
        float m = -1e30f;
        for (int v = v0; v < v1; v++) m = fmaxf(m, C[(size_t)v*CS + t]);
        pm[slice*80 + t] = m;
    }
    // row max over valid t, 0-clamped when masked positions exist
    float rm = 0.f;
    if (tid < NV){
        float m = -1e30f;
        for (int t = 0; t < len; t++) m = fmaxf(m, C[(size_t)tid*CS + t]);
        if (len < NT) m = fmaxf(m, 0.f);
        rm = m;
    }
    __syncthreads();
    if (tid < 80) cm[tid] = fmaxf(fmaxf(pm[tid], pm[80+tid]), pm[160+tid]);
    #pragma unroll
    for (int o = 16; o > 0; o >>= 1) rm += __shfl_xor_sync(0xffffffffu, rm, o);
    if (lane == 0) red[warp] = rm;
    __syncthreads();
    if (warp == 0){
        float s = (lane < 8) ? red[lane] : 0.f;
        #pragma unroll
        for (int o = 4; o > 0; o >>= 1) s += __shfl_xor_sync(0xffffffffu, s, o);
        float ts = 0.f;
        for (int t = lane; t < len; t += 32) ts += cm[t];
        #pragma unroll
        for (int o = 16; o > 0; o >>= 1) ts += __shfl_xor_sync(0xffffffffu, ts, o);
        if (lane == 0){
            out[2*NB*NE            + (size_t)b*NQ + q] = ts / (float)len;  // t2v
            out[2*NB*NE + NB*NQ    + (size_t)b*NQ + q] = s / (float)NV;    // v2t
        }
    }
}

extern "C" void kernel_launch(void* const* d_in, const int* in_sizes, int n_in,
                              void* d_out, int out_size) {
    const float* visual_cls    = (const float*)d_in[0];
    const float* visual_tokens = (const float*)d_in[1];
    const float* textual_cls   = (const float*)d_in[2];
    const float* textual_tokens= (const float*)d_in[3];
    const float* Wv_cls = (const float*)d_in[4];
    const float* bv_cls = (const float*)d_in[5];
    const float* Wt_cls = (const float*)d_in[6];
    const float* bt_cls = (const float*)d_in[7];
    const float* Wv_tok = (const float*)d_in[8];
    const float* bv_tok = (const float*)d_in[9];
    const float* Wt_tok = (const float*)d_in[10];
    const float* bt_tok = (const float*)d_in[11];
    const int*   text_length = (const int*)d_in[12];
    float* out = (float*)d_out;

    static bool attr_done = false;
    if (!attr_done){
        cudaFuncSetAttribute(fg_kernel, cudaFuncAttributeMaxDynamicSharedMemorySize, FG_SMEM);
        attr_done = true;
    }

    cls_gemm<<<dim3(6,8,2), 256>>>(visual_cls, textual_cls,
                                   Wv_cls, bv_cls, Wt_cls, bt_cls, out);
    tok_gemm<<<dim3((RV+127)/128, 4), 256>>>(visual_tokens, Wv_tok, bv_tok, RV, 0);
    tok_gemm<<<dim3((RT+127)/128, 4), 256>>>(textual_tokens, Wt_tok, bt_tok, RT, 1);
    norm_kernel<<<RV/8, 256>>>(RV, 0);
    norm_kernel<<<RT/8, 256>>>(RT, 1);
    fg_kernel<<<dim3(NQ, NB), 256, FG_SMEM>>>(text_length, out);
}

// round 5
// speedup vs baseline: 1.0700x; 1.0700x over previous
#include <cuda_runtime.h>
#include <cuda_bf16.h>
#include <stdint.h>

#define NB 96
#define NQ 96
#define NV 197
#define NT 77
#define ND 768
#define NE 512
#define RV (NB*NV)
#define RT (NQ*NT)

// scratch (static device globals — no allocation allowed)
__device__ float g_Pv[RV*NE];
__device__ float g_Pt[RT*NE];
__device__ __nv_bfloat16 g_vtok[RV*NE];
__device__ __nv_bfloat16 g_ttok[RT*NE];

__device__ __forceinline__ uint32_t smem_u32(const void* p){
    return (uint32_t)__cvta_generic_to_shared(p);
}
__device__ __forceinline__ void cp16(uint32_t dst, const void* src, int sz){
    asm volatile("cp.async.cg.shared.global [%0], [%1], 16, %2;\n"
                 :: "r"(dst), "l"(src), "r"(sz));
}
__device__ __forceinline__ void cp_commit(){ asm volatile("cp.async.commit_group;\n"); }
template<int N> __device__ __forceinline__ void cp_wait(){
    asm volatile("cp.async.wait_group %0;\n" :: "n"(N));
}
__device__ __forceinline__ uint32_t f2tf(float f){
    uint32_t u; asm("cvt.rna.tf32.f32 %0, %1;\n" : "=r"(u) : "f"(f)); return u;
}
__device__ __forceinline__ void mma_bf16(float c[4], const uint32_t a[4], const uint32_t b[2]){
    asm volatile(
      "mma.sync.aligned.m16n8k16.row.col.f32.bf16.bf16.f32 "
      "{%0,%1,%2,%3},{%4,%5,%6,%7},{%8,%9},{%0,%1,%2,%3};\n"
      : "+f"(c[0]),"+f"(c[1]),"+f"(c[2]),"+f"(c[3])
      : "r"(a[0]),"r"(a[1]),"r"(a[2]),"r"(a[3]),"r"(b[0]),"r"(b[1]));
}
__device__ __forceinline__ void mma_tf32(float c[4], const uint32_t a[4], const uint32_t b[2]){
    asm volatile(
      "mma.sync.aligned.m16n8k8.row.col.f32.tf32.tf32.f32 "
      "{%0,%1,%2,%3},{%4,%5,%6,%7},{%8,%9},{%0,%1,%2,%3};\n"
      : "+f"(c[0]),"+f"(c[1]),"+f"(c[2]),"+f"(c[3])
      : "r"(a[0]),"r"(a[1]),"r"(a[2]),"r"(a[3]),"r"(b[0]),"r"(b[1]));
}
__device__ __forceinline__ void ldsm_x4(uint32_t r[4], uint32_t addr){
    asm volatile("ldmatrix.sync.aligned.m8n8.x4.shared.b16 {%0,%1,%2,%3}, [%4];"
                 : "=r"(r[0]), "=r"(r[1]), "=r"(r[2]), "=r"(r[3]) : "r"(addr));
}
__device__ __forceinline__ void ldsm_x2(uint32_t r[2], uint32_t addr){
    asm volatile("ldmatrix.sync.aligned.m8n8.x2.shared.b16 {%0,%1}, [%2];"
                 : "=r"(r[0]), "=r"(r[1]) : "r"(addr));
}

// ---------------------------------------------------------------------------
// K1: cls projections (pure FP32, accuracy-critical outputs)
// ---------------------------------------------------------------------------
__global__ __launch_bounds__(256) void cls_gemm(
    const float* __restrict__ Xv, const float* __restrict__ Xt,
    const float* __restrict__ Wv, const float* __restrict__ bv,
    const float* __restrict__ Wt, const float* __restrict__ bt,
    float* __restrict__ out)
{
    __shared__ float Xs[16][64];
    __shared__ float Ws[64][65];
    const int which = blockIdx.z;
    const float* X    = which ? Xt : Xv;
    const float* W    = which ? Wt : Wv;
    const float* bias = which ? bt : bv;
    const int m0 = blockIdx.x * 16;
    const int n0 = blockIdx.y * 64;
    const int tid = threadIdx.x;
    float acc[4] = {0.f,0.f,0.f,0.f};
    const int jj = tid & 63;
    const int r4 = (tid >> 6) * 4;

    for (int k0 = 0; k0 < ND; k0 += 64){
        {
            int r = tid >> 4, kv = tid & 15;
            float4 x4 = *(const float4*)(X + (size_t)(m0 + r)*ND + k0 + kv*4);
            Xs[r][kv*4+0]=x4.x; Xs[r][kv*4+1]=x4.y; Xs[r][kv*4+2]=x4.z; Xs[r][kv*4+3]=x4.w;
        }
        #pragma unroll
        for (int i = 0; i < 4; i++){
            int seg = tid + 256*i; int r = seg >> 4, kv = seg & 15;
            float4 w4 = *(const float4*)(W + (size_t)(n0 + r)*ND + k0 + kv*4);
            Ws[r][kv*4+0]=w4.x; Ws[r][kv*4+1]=w4.y; Ws[r][kv*4+2]=w4.z; Ws[r][kv*4+3]=w4.w;
        }
        __syncthreads();
        #pragma unroll
        for (int k = 0; k < 64; k++){
            float w = Ws[jj][k];
            acc[0] += Xs[r4+0][k]*w;
            acc[1] += Xs[r4+1][k]*w;
            acc[2] += Xs[r4+2][k]*w;
            acc[3] += Xs[r4+3][k]*w;
        }
        __syncthreads();
    }
    float bb = bias[n0 + jj];
    float* o = out + (size_t)which*(NB*NE);
    #pragma unroll
    for (int i = 0; i < 4; i++)
        o[(size_t)(m0 + r4 + i)*NE + n0 + jj] = acc[i] + bb;
}

// ---------------------------------------------------------------------------
// K2: token projection GEMM (TF32 mma.sync m16n8k8)
// ---------------------------------------------------------------------------
__global__ __launch_bounds__(256,2) void tok_gemm(
    const float* __restrict__ X, const float* __restrict__ W,
    const float* __restrict__ bias, int R, int which)
{
    __shared__ float As[2][128][20];
    __shared__ float Bs[2][128][20];
    float* P = which ? g_Pt : g_Pv;
    const int m0 = blockIdx.x*128, n0 = blockIdx.y*128;
    const int tid = threadIdx.x, lane = tid & 31, warp = tid >> 5;
    const int wm = warp & 1, wn = warp >> 1;
    float acc[4][4][4] = {};
    const uint32_t aB = smem_u32(&As[0][0][0]);
    const uint32_t bB = smem_u32(&Bs[0][0][0]);

    auto loadP = [&](int buf, int kc){
        const int k0 = kc*16;
        #pragma unroll
        for (int i = 0; i < 2; i++){
            int seg = tid + 256*i; int r = seg >> 2, kv = seg & 3;
            uint32_t dst = aB + (uint32_t)(buf*128*20 + r*20 + kv*4)*4;
            int gr = m0 + r;
            const float* src = X + (size_t)(gr < R ? gr : 0)*ND + k0 + kv*4;
            cp16(dst, src, gr < R ? 16 : 0);
        }
        #pragma unroll
        for (int i = 0; i < 2; i++){
            int seg = tid + 256*i; int r = seg >> 2, kv = seg & 3;
            uint32_t dst = bB + (uint32_t)(buf*128*20 + r*20 + kv*4)*4;
            const float* src = W + (size_t)(n0 + r)*ND + k0 + kv*4;
            cp16(dst, src, 16);
        }
    };

    loadP(0, 0); cp_commit();
    for (int kc = 0; kc < 48; kc++){
        if (kc < 47){ loadP((kc+1)&1, kc+1); cp_commit(); cp_wait<1>(); }
        else        { cp_wait<0>(); }
        __syncthreads();
        const int buf = kc & 1;
        #pragma unroll
        for (int ks = 0; ks < 2; ks++){
            const int kk = ks*8 + (lane & 3);
            uint32_t a[4][4], bfr[4][2];
            #pragma unroll
            for (int mt = 0; mt < 4; mt++){
                int r = wm*64 + mt*16 + (lane >> 2);
                a[mt][0] = f2tf(As[buf][r  ][kk  ]);
                a[mt][1] = f2tf(As[buf][r+8][kk  ]);
                a[mt][2] = f2tf(As[buf][r  ][kk+4]);
                a[mt][3] = f2tf(As[buf][r+8][kk+4]);
            }
            #pragma unroll
            for (int nt = 0; nt < 4; nt++){
                int n = wn*32 + nt*8 + (lane >> 2);
                bfr[nt][0] = f2tf(Bs[buf][n][kk  ]);
                bfr[nt][1] = f2tf(Bs[buf][n][kk+4]);
            }
            #pragma unroll
            for (int mt = 0; mt < 4; mt++)
                #pragma unroll
                for (int nt = 0; nt < 4; nt++)
                    mma_tf32(acc[mt][nt], a[mt], bfr[nt]);
        }
        __syncthreads();
    }
    #pragma unroll
    for (int mt = 0; mt < 4; mt++){
        #pragma unroll
        for (int nt = 0; nt < 4; nt++){
            int r = m0 + wm*64 + mt*16 + (lane >> 2);
            int c = n0 + wn*32 + nt*8 + (lane & 3)*2;
            float b0 = bias[c], b1 = bias[c+1];
            if (r < R){
                P[(size_t)r*NE + c  ] = acc[mt][nt][0] + b0;
                P[(size_t)r*NE + c+1] = acc[mt][nt][1] + b1;
            }
            if (r + 8 < R){
                P[(size_t)(r+8)*NE + c  ] = acc[mt][nt][2] + b0;
                P[(size_t)(r+8)*NE + c+1] = acc[mt][nt][3] + b1;
            }
        }
    }
}

// ---------------------------------------------------------------------------
// K3: l2-normalize rows of P -> bf16 tokens
// ---------------------------------------------------------------------------
__global__ __launch_bounds__(256) void norm_kernel(int R, int which)
{
    const float* P = which ? g_Pt : g_Pv;
    __nv_bfloat16* O = which ? g_ttok : g_vtok;
    const int row  = blockIdx.x*8 + (threadIdx.x >> 5);
    const int lane = threadIdx.x & 31;
    if (row >= R) return;
    const float4* p = (const float4*)(P + (size_t)row*NE);
    float4 v[4]; float ss = 0.f;
    #pragma unroll
    for (int i = 0; i < 4; i++){
        v[i] = p[lane + 32*i];
        ss += v[i].x*v[i].x + v[i].y*v[i].y + v[i].z*v[i].z + v[i].w*v[i].w;
    }
    #pragma unroll
    for (int o = 16; o > 0; o >>= 1) ss += __shfl_xor_sync(0xffffffffu, ss, o);
    const float s = 1.f / fmaxf(sqrtf(ss), 1e-12f);
    uint2* ob = (uint2*)(O + (size_t)row*NE);
    #pragma unroll
    for (int i = 0; i < 4; i++){
        __nv_bfloat162 lo = __floats2bfloat162_rn(v[i].x*s, v[i].y*s);
        __nv_bfloat162 hi = __floats2bfloat162_rn(v[i].z*s, v[i].w*s);
        uint2 u; u.x = *(uint32_t*)&lo; u.y = *(uint32_t*)&hi;
        ob[lane + 32*i] = u;
    }
}

// ---------------------------------------------------------------------------
// K4: fused fine-grained similarity + masked reductions (mma.sync + ldmatrix).
// One CTA per (q, b). C[256pad, 80pad] = v_tok[b] @ t_tok[q]^T via bf16
// m16n8k16, K=512 in 8 chunks of 64, double-buffered cp.async.
// Epilogue entirely in registers: per-fragment masked row/col max + shfl
// butterflies + tiny smem partials (overlaid on the A buffer).
// 2 CTAs/SM (smem 94.5KB x2, regs capped at 128).
// ---------------------------------------------------------------------------
#define FG_SMEM 96768
#define ASTRIDE 144          // 72 bf16 per row

__global__ __launch_bounds__(256,2) void fg3_kernel(
    const int* __restrict__ text_length, float* __restrict__ out)
{
    extern __shared__ char smem[];
    // [0, 73728): As[2][256][72] bf16 ; [73728, 96768): Bs[2][80][72] bf16
    const uint32_t aB = smem_u32(smem);
    const uint32_t bB = aB + 73728;
    float* rowp = (float*)smem;            // [2][256]  (epilogue overlay)
    float* colp = (float*)(smem + 2048);   // [4][80]
    float* red  = (float*)(smem + 3328);   // [8]

    const int q = blockIdx.x, b = blockIdx.y;
    const int tid = threadIdx.x, lane = tid & 31, warp = tid >> 5;
    const int wm = warp >> 1, wn = warp & 1;   // 4 x 2 warps: 64 rows x 40 cols
    const __nv_bfloat16* Ag = g_vtok + (size_t)b*NV*NE;
    const __nv_bfloat16* Bg = g_ttok + (size_t)q*NT*NE;
    float acc[4][5][4] = {};

    // per-thread ldmatrix base addresses (buffer 0)
    const uint32_t a_lane = aB + (uint32_t)(wm*64 + (lane & 15))*ASTRIDE
                               + (uint32_t)((lane >> 4) & 1)*16;
    const uint32_t b_lane = bB + (uint32_t)(wn*40 + (lane & 7) + ((lane >> 4) & 1)*8)*ASTRIDE
                               + (uint32_t)((lane >> 3) & 1)*16;

    auto loadc = [&](int buf, int kc){
        const int k0 = kc*64;
        #pragma unroll
        for (int i = 0; i < 8; i++){           // A: 256 rows x 128B
            int seg = tid + 256*i; int r = seg >> 3, kv = seg & 7;
            uint32_t dst = aB + (uint32_t)buf*36864 + (uint32_t)r*ASTRIDE + (uint32_t)kv*16;
            const __nv_bfloat16* src = Ag + (size_t)(r < NV ? r : 0)*NE + k0 + kv*8;
            cp16(dst, src, r < NV ? 16 : 0);
        }
        #pragma unroll
        for (int i = 0; i < 3; i++){           // B: 80 rows x 128B
            int seg = tid + 256*i;
            if (seg < 640){
                int r = seg >> 3, kv = seg & 7;
                uint32_t dst = bB + (uint32_t)buf*11520 + (uint32_t)r*ASTRIDE + (uint32_t)kv*16;
                const __nv_bfloat16* src = Bg + (size_t)(r < NT ? r : 0)*NE + k0 + kv*8;
                cp16(dst, src, r < NT ? 16 : 0);
            }
        }
    };

    loadc(0, 0); cp_commit();
    for (int kc = 0; kc < 8; kc++){
        if (kc < 7){ loadc((kc+1)&1, kc+1); cp_commit(); cp_wait<1>(); }
        else       { cp_wait<0>(); }
        __syncthreads();
        const uint32_t abuf = a_lane + (uint32_t)(kc & 1)*36864;
        const uint32_t bbuf = b_lane + (uint32_t)(kc & 1)*11520;
        #pragma unroll
        for (int ks = 0; ks < 4; ks++){
            const uint32_t ko = (uint32_t)ks*32;
            uint32_t a[4][4], bfr[10];
            #pragma unroll
            for (int mt = 0; mt < 4; mt++)
                ldsm_x4(a[mt], abuf + (uint32_t)mt*(16*ASTRIDE) + ko);
            ldsm_x4(&bfr[0], bbuf + ko);                        // nt 0,1
            ldsm_x4(&bfr[4], bbuf + 16*ASTRIDE + ko);           // nt 2,3
            ldsm_x2(&bfr[8], bbuf + 32*ASTRIDE + ko);           // nt 4
            #pragma unroll
            for (int mt = 0; mt < 4; mt++)
                #pragma unroll
                for (int nt = 0; nt < 5; nt++)
                    mma_bf16(acc[mt][nt], a[mt], &bfr[nt*2]);
        }
        __syncthreads();
    }

    // ---- epilogue: register-space masked reductions ----
    const int len = text_length[q];
    const float NEG = -3.0e38f;

    // row maxima (over this warp's 40 cols, masked to c < len)
    #pragma unroll
    for (int mt = 0; mt < 4; mt++){
        float m0 = NEG, m1 = NEG;
        #pragma unroll
        for (int nt = 0; nt < 5; nt++){
            int c0 = wn*40 + nt*8 + (lane & 3)*2;
            if (c0 < len){ m0 = fmaxf(m0, acc[mt][nt][0]); m1 = fmaxf(m1, acc[mt][nt][2]); }
            if (c0 + 1 < len){ m0 = fmaxf(m0, acc[mt][nt][1]); m1 = fmaxf(m1, acc[mt][nt][3]); }
        }
        m0 = fmaxf(m0, __shfl_xor_sync(0xffffffffu, m0, 1));
        m0 = fmaxf(m0, __shfl_xor_sync(0xffffffffu, m0, 2));
        m1 = fmaxf(m1, __shfl_xor_sync(0xffffffffu, m1, 1));
        m1 = fmaxf(m1, __shfl_xor_sync(0xffffffffu, m1, 2));
        if ((lane & 3) == 0){
            int r = wm*64 + mt*16 + (lane >> 2);
            rowp[wn*256 + r]     = m0;
            rowp[wn*256 + r + 8] = m1;
        }
    }
    // column maxima (over this warp's 64 rows, masked to r < NV)
    #pragma unroll
    for (int nt = 0; nt < 5; nt++){
        float c0m = NEG, c1m = NEG;
        #pragma unroll
        for (int mt = 0; mt < 4; mt++){
            int r = wm*64 + mt*16 + (lane >> 2);
            if (r < NV){ c0m = fmaxf(c0m, acc[mt][nt][0]); c1m = fmaxf(c1m, acc[mt][nt][1]); }
            if (r + 8 < NV){ c0m = fmaxf(c0m, acc[mt][nt][2]); c1m = fmaxf(c1m, acc[mt][nt][3]); }
        }
        #pragma unroll
        for (int o = 4; o <= 16; o <<= 1){
            c0m = fmaxf(c0m, __shfl_xor_sync(0xffffffffu, c0m, o));
            c1m = fmaxf(c1m, __shfl_xor_sync(0xffffffffu, c1m, o));
        }
        if (lane < 4){
            int c = wn*40 + nt*8 + lane*2;
            colp[wm*80 + c]     = c0m;
            colp[wm*80 + c + 1] = c1m;
        }
    }
    __syncthreads();

    // v2t: sum over valid v rows of max(rowp[0], rowp[1]) (0-clamped if len<T)
    float contrib = 0.f;
    if (tid < NV){
        float r = fmaxf(rowp[tid], rowp[256 + tid]);
        if (len < NT) r = fmaxf(r, 0.f);
        contrib = r;
    }
    #pragma unroll
    for (int o = 16; o > 0; o >>= 1) contrib += __shfl_xor_sync(0xffffffffu, contrib, o);
    if (lane == 0) red[warp] = contrib;
    __syncthreads();
    if (warp == 0){
        float s = (lane < 8) ? red[lane] : 0.f;
        #pragma unroll
        for (int o = 4; o > 0; o >>= 1) s += __shfl_xor_sync(0xffffffffu, s, o);
        float ts = 0.f;
        for (int t = lane; t < len; t += 32){
            float cm = fmaxf(fmaxf(colp[t], colp[80 + t]),
                             fmaxf(colp[160 + t], colp[240 + t]));
            ts += cm;
        }
        #pragma unroll
        for (int o = 16; o > 0; o >>= 1) ts += __shfl_xor_sync(0xffffffffu, ts, o);
        if (lane == 0){
            out[2*NB*NE         + (size_t)b*NQ + q] = ts / (float)len;  // t2v
            out[2*NB*NE + NB*NQ + (size_t)b*NQ + q] = s / (float)NV;    // v2t
        }
    }
}

extern "C" void kernel_launch(void* const* d_in, const int* in_sizes, int n_in,
                              void* d_out, int out_size) {
    const float* visual_cls    = (const float*)d_in[0];
    const float* visual_tokens = (const float*)d_in[1];
    const float* textual_cls   = (const float*)d_in[2];
    const float* textual_tokens= (const float*)d_in[3];
    const float* Wv_cls = (const float*)d_in[4];
    const float* bv_cls = (const float*)d_in[5];
    const float* Wt_cls = (const float*)d_in[6];
    const float* bt_cls = (const float*)d_in[7];
    const float* Wv_tok = (const float*)d_in[8];
    const float* bv_tok = (const float*)d_in[9];
    const float* Wt_tok = (const float*)d_in[10];
    const float* bt_tok = (const float*)d_in[11];
    const int*   text_length = (const int*)d_in[12];
    float* out = (float*)d_out;

    static bool attr_done = false;
    if (!attr_done){
        cudaFuncSetAttribute(fg3_kernel, cudaFuncAttributeMaxDynamicSharedMemorySize, FG_SMEM);
        attr_done = true;
    }

    cls_gemm<<<dim3(6,8,2), 256>>>(visual_cls, textual_cls,
                                   Wv_cls, bv_cls, Wt_cls, bt_cls, out);
    tok_gemm<<<dim3((RV+127)/128, 4), 256>>>(visual_tokens, Wv_tok, bv_tok, RV, 0);
    tok_gemm<<<dim3((RT+127)/128, 4), 256>>>(textual_tokens, Wt_tok, bt_tok, RT, 1);
    norm_kernel<<<RV/8, 256>>>(RV, 0);
    norm_kernel<<<RT/8, 256>>>(RT, 1);
    fg3_kernel<<<dim3(NQ, NB), 256, FG_SMEM>>>(text_length, out);
}